// round 7
// baseline (speedup 1.0000x reference)
#include <cuda_runtime.h>
#include <math.h>

#define DIMV 512
#define HIDV 2048
#define NBATCH 4
#define SLV 4096
#define TOK (NBATCH*SLV)          // 16384
#define SA 132                    // smem row stride (128 + 4 pad), 132*4B % 16 == 0

// ---------------- scratch (device globals: no allocation allowed) ----------------
__device__ float g_Wk[DIMV*DIMV];
__device__ float g_Wv[DIMV*DIMV];
__device__ float g_Wo[DIMV*DIMV];
__device__ float g_W1[HIDV*DIMV];
__device__ float g_W2[DIMV*HIDV];
__device__ float g_xk[TOK*DIMV];
__device__ float g_xv[TOK*DIMV];
__device__ float g_h[TOK*DIMV];
__device__ float g_hres[TOK*DIMV];
__device__ float g_ff1[TOK*HIDV];                 // 33.5M floats
__device__ float g_scores[NBATCH*SLV*SLV];        // 67.1M floats (268 MB)
__device__ unsigned char g_flags[32*32];          // 1 = tile fully masked (<= -1e8)

// ---------------- f32x2 helpers (Blackwell packed fp32 FMA) ----------------
__device__ __forceinline__ void ffma2(unsigned long long &d, unsigned long long a, unsigned long long b){
    asm("fma.rn.f32x2 %0, %1, %2, %0;" : "+l"(d) : "l"(a), "l"(b));
}
__device__ __forceinline__ unsigned long long pk2(float x){
    unsigned long long r; asm("mov.b64 %0, {%1, %1};" : "=l"(r) : "f"(x)); return r;
}
union F2U { unsigned long long u; float2 f; };

// transpose-store a float4 (4 consecutive k) of one row into As[k][m]
__device__ __forceinline__ void sts4t(float* s, int k, int m, float4 v){
    s[(k+0)*SA+m]=v.x; s[(k+1)*SA+m]=v.y; s[(k+2)*SA+m]=v.z; s[(k+3)*SA+m]=v.w;
}

// 16-step inner product on one smem tile pair; acc pairs along n (low lane = even col)
__device__ __forceinline__ void mm16(const float* __restrict__ As, const float* __restrict__ Bs,
                                     int m0, int n0, unsigned long long (&acc)[8][4]){
    #pragma unroll
    for (int kk=0; kk<16; kk++){
        const float* ar = As + kk*SA + m0;
        float4 a0 = *(const float4*)(ar);
        float4 a1 = *(const float4*)(ar+4);
        const float* br = Bs + kk*SA + n0;
        ulonglong2 q0 = *(const ulonglong2*)(br);
        ulonglong2 q1 = *(const ulonglong2*)(br+4);
        unsigned long long b0=q0.x, b1=q0.y, b2=q1.x, b3=q1.y;
        unsigned long long a;
        a=pk2(a0.x); ffma2(acc[0][0],a,b0); ffma2(acc[0][1],a,b1); ffma2(acc[0][2],a,b2); ffma2(acc[0][3],a,b3);
        a=pk2(a0.y); ffma2(acc[1][0],a,b0); ffma2(acc[1][1],a,b1); ffma2(acc[1][2],a,b2); ffma2(acc[1][3],a,b3);
        a=pk2(a0.z); ffma2(acc[2][0],a,b0); ffma2(acc[2][1],a,b1); ffma2(acc[2][2],a,b2); ffma2(acc[2][3],a,b3);
        a=pk2(a0.w); ffma2(acc[3][0],a,b0); ffma2(acc[3][1],a,b1); ffma2(acc[3][2],a,b2); ffma2(acc[3][3],a,b3);
        a=pk2(a1.x); ffma2(acc[4][0],a,b0); ffma2(acc[4][1],a,b1); ffma2(acc[4][2],a,b2); ffma2(acc[4][3],a,b3);
        a=pk2(a1.y); ffma2(acc[5][0],a,b0); ffma2(acc[5][1],a,b1); ffma2(acc[5][2],a,b2); ffma2(acc[5][3],a,b3);
        a=pk2(a1.z); ffma2(acc[6][0],a,b0); ffma2(acc[6][1],a,b1); ffma2(acc[6][2],a,b2); ffma2(acc[6][3],a,b3);
        a=pk2(a1.w); ffma2(acc[7][0],a,b0); ffma2(acc[7][1],a,b1); ffma2(acc[7][2],a,b2); ffma2(acc[7][3],a,b3);
    }
}

// ---------------- weight materialization: W = mu + exp(ls)*eps ----------------
__global__ void make_w_kernel(const float* __restrict__ mu, const float* __restrict__ ls,
                              const float* __restrict__ eps, float* __restrict__ w, int n){
    int i = blockIdx.x*256 + threadIdx.x;
    if (i < n) w[i] = fmaf(expf(ls[i]), eps[i], mu[i]);
}

// ---------------- flags: 1 if whole 128x128 mask tile <= -1e8 ----------------
__global__ void flags_kernel(const float* __restrict__ mask){
    int qb=blockIdx.y, kb=blockIdx.x, tid=threadIdx.x;
    int any = 0;
    #pragma unroll 4
    for (int i=0;i<64;i++){
        int idx=i*256+tid; int r=idx>>7, c=idx&127;
        float v = mask[(size_t)(qb*128+r)*SLV + kb*128+c];
        any |= (v > -1e8f) ? 1 : 0;
    }
    int a = __syncthreads_or(any);
    if (tid==0) g_flags[qb*32+kb] = (a==0) ? 1 : 0;
}

// ---------------- generic NT GEMM: C[M,N] = A[M,K] * B[N,K]^T (+epilogue) ----------------
// epi: 0 = none, 1 = C += aux (same layout), 2 = relu
__global__ void __launch_bounds__(256,2)
gemm_nt_kernel(const float* __restrict__ A, const float* __restrict__ B,
               float* __restrict__ C, const float* __restrict__ aux,
               int M, int N, int K, int epi)
{
    (void)M;
    __shared__ __align__(16) float As[2][16*SA];
    __shared__ __align__(16) float Bs[2][16*SA];
    const int tid = threadIdx.x;
    const int bm = blockIdx.y*128;
    const int bn = blockIdx.x*128;

    const int c0=tid, c1=tid+256;
    const int r0=c0>>2, k0=(c0&3)*4;
    const int r1=c1>>2, k1=(c1&3)*4;
    const float* pa0 = A + (size_t)(bm+r0)*K + k0;
    const float* pa1 = A + (size_t)(bm+r1)*K + k1;
    const float* pb0 = B + (size_t)(bn+r0)*K + k0;
    const float* pb1 = B + (size_t)(bn+r1)*K + k1;

    const int tx=tid&15, ty=tid>>4;
    const int m0=ty*8, n0=tx*8;

    unsigned long long acc[8][4];
    #pragma unroll
    for (int i=0;i<8;i++){
        #pragma unroll
        for (int j=0;j<4;j++) acc[i][j]=0ull;
    }

    const int nt = K>>4;
    float4 ra0 = *(const float4*)pa0;
    float4 ra1 = *(const float4*)pa1;
    float4 rb0 = *(const float4*)pb0;
    float4 rb1 = *(const float4*)pb1;
    sts4t(As[0],k0,r0,ra0); sts4t(As[0],k1,r1,ra1);
    sts4t(Bs[0],k0,r0,rb0); sts4t(Bs[0],k1,r1,rb1);
    __syncthreads();

    for (int t=0; t<nt; t++){
        if (t+1 < nt){
            int ko=(t+1)*16;
            ra0 = *(const float4*)(pa0+ko);
            ra1 = *(const float4*)(pa1+ko);
            rb0 = *(const float4*)(pb0+ko);
            rb1 = *(const float4*)(pb1+ko);
        }
        mm16(As[t&1], Bs[t&1], m0, n0, acc);
        if (t+1 < nt){
            float* a2=As[(t+1)&1]; float* b2=Bs[(t+1)&1];
            sts4t(a2,k0,r0,ra0); sts4t(a2,k1,r1,ra1);
            sts4t(b2,k0,r0,rb0); sts4t(b2,k1,r1,rb1);
            __syncthreads();
        }
    }

    #pragma unroll
    for (int i=0;i<8;i++){
        size_t off = (size_t)(bm+m0+i)*N + bn + n0;
        F2U u0,u1,u2,u3;
        u0.u=acc[i][0]; u1.u=acc[i][1]; u2.u=acc[i][2]; u3.u=acc[i][3];
        float4 o0 = make_float4(u0.f.x,u0.f.y,u1.f.x,u1.f.y);
        float4 o1 = make_float4(u2.f.x,u2.f.y,u3.f.x,u3.f.y);
        if (epi==1){
            float4 x0 = *(const float4*)(aux+off);
            float4 x1 = *(const float4*)(aux+off+4);
            o0.x+=x0.x; o0.y+=x0.y; o0.z+=x0.z; o0.w+=x0.w;
            o1.x+=x1.x; o1.y+=x1.y; o1.z+=x1.z; o1.w+=x1.w;
        } else if (epi==2){
            o0.x=fmaxf(o0.x,0.f); o0.y=fmaxf(o0.y,0.f); o0.z=fmaxf(o0.z,0.f); o0.w=fmaxf(o0.w,0.f);
            o1.x=fmaxf(o1.x,0.f); o1.y=fmaxf(o1.y,0.f); o1.z=fmaxf(o1.z,0.f); o1.w=fmaxf(o1.w,0.f);
        }
        *(float4*)(C+off)=o0; *(float4*)(C+off+4)=o1;
    }
}

// ---------------- scores: S[b] = (x[b] @ xk[b]^T)/sqrt(D) + mask, skip fully-masked tiles --------
__global__ void __launch_bounds__(256,2)
scores_kernel(const float* __restrict__ x, const float* __restrict__ mask)
{
    const int b = blockIdx.z, qb=blockIdx.y, kb=blockIdx.x;
    if (g_flags[qb*32+kb]) return;
    const float* A = x   + (size_t)b*SLV*DIMV;
    const float* B = g_xk + (size_t)b*SLV*DIMV;

    __shared__ __align__(16) float As[2][16*SA];
    __shared__ __align__(16) float Bs[2][16*SA];
    const int tid = threadIdx.x;
    const int bm = qb*128, bn = kb*128;

    const int c0=tid, c1=tid+256;
    const int r0=c0>>2, k0=(c0&3)*4;
    const int r1=c1>>2, k1=(c1&3)*4;
    const float* pa0 = A + (size_t)(bm+r0)*DIMV + k0;
    const float* pa1 = A + (size_t)(bm+r1)*DIMV + k1;
    const float* pb0 = B + (size_t)(bn+r0)*DIMV + k0;
    const float* pb1 = B + (size_t)(bn+r1)*DIMV + k1;

    const int tx=tid&15, ty=tid>>4;
    const int m0=ty*8, n0=tx*8;

    unsigned long long acc[8][4];
    #pragma unroll
    for (int i=0;i<8;i++){
        #pragma unroll
        for (int j=0;j<4;j++) acc[i][j]=0ull;
    }

    const int nt = DIMV>>4;   // 32
    float4 ra0 = *(const float4*)pa0;
    float4 ra1 = *(const float4*)pa1;
    float4 rb0 = *(const float4*)pb0;
    float4 rb1 = *(const float4*)pb1;
    sts4t(As[0],k0,r0,ra0); sts4t(As[0],k1,r1,ra1);
    sts4t(Bs[0],k0,r0,rb0); sts4t(Bs[0],k1,r1,rb1);
    __syncthreads();

    for (int t=0; t<nt; t++){
        if (t+1 < nt){
            int ko=(t+1)*16;
            ra0 = *(const float4*)(pa0+ko);
            ra1 = *(const float4*)(pa1+ko);
            rb0 = *(const float4*)(pb0+ko);
            rb1 = *(const float4*)(pb1+ko);
        }
        mm16(As[t&1], Bs[t&1], m0, n0, acc);
        if (t+1 < nt){
            float* a2=As[(t+1)&1]; float* b2=Bs[(t+1)&1];
            sts4t(a2,k0,r0,ra0); sts4t(a2,k1,r1,ra1);
            sts4t(b2,k0,r0,rb0); sts4t(b2,k1,r1,rb1);
            __syncthreads();
        }
    }

    const float sc = 0.04419417382415922f;   // 1/sqrt(512)
    float* S = g_scores + (size_t)b*SLV*SLV;
    #pragma unroll
    for (int i=0;i<8;i++){
        size_t moff = (size_t)(bm+m0+i)*SLV + bn + n0;
        F2U u0,u1,u2,u3;
        u0.u=acc[i][0]; u1.u=acc[i][1]; u2.u=acc[i][2]; u3.u=acc[i][3];
        float4 mk0 = *(const float4*)(mask+moff);
        float4 mk1 = *(const float4*)(mask+moff+4);
        float4 o0, o1;
        o0.x = u0.f.x*sc + mk0.x; o0.y = u0.f.y*sc + mk0.y;
        o0.z = u1.f.x*sc + mk0.z; o0.w = u1.f.y*sc + mk0.w;
        o1.x = u2.f.x*sc + mk1.x; o1.y = u2.f.y*sc + mk1.y;
        o1.z = u3.f.x*sc + mk1.z; o1.w = u3.f.y*sc + mk1.w;
        *(float4*)(S+moff)   = o0;
        *(float4*)(S+moff+4) = o1;
    }
}

// ---------------- row softmax (in place), skipping fully-masked tiles ----------------
__global__ void __launch_bounds__(256)
softmax_kernel()
{
    const int row = blockIdx.x;            // b*SLV + q
    const int q = row & (SLV-1);
    const int qb = q >> 7;
    const int tid = threadIdx.x;
    __shared__ unsigned char fl[32];
    __shared__ float red[8];
    if (tid < 32) fl[tid] = g_flags[qb*32 + tid];
    __syncthreads();
    float* S = g_scores + (size_t)row*SLV;

    float vals[16];
    float mx = -3.402823466e38f;
    #pragma unroll
    for (int i=0;i<16;i++){
        int idx = i*256 + tid;
        float v = fl[idx>>7] ? -3.402823466e38f : S[idx];
        vals[i] = v; mx = fmaxf(mx, v);
    }
    #pragma unroll
    for (int o=16;o>0;o>>=1) mx = fmaxf(mx, __shfl_xor_sync(0xffffffffu, mx, o));
    if ((tid&31)==0) red[tid>>5] = mx;
    __syncthreads();
    float m = red[0];
    #pragma unroll
    for (int w=1;w<8;w++) m = fmaxf(m, red[w]);
    __syncthreads();

    float s = 0.f;
    #pragma unroll
    for (int i=0;i<16;i++){ float e = expf(vals[i]-m); vals[i]=e; s+=e; }
    #pragma unroll
    for (int o=16;o>0;o>>=1) s += __shfl_xor_sync(0xffffffffu, s, o);
    if ((tid&31)==0) red[tid>>5] = s;
    __syncthreads();
    float tot = 0.f;
    #pragma unroll
    for (int w=0;w<8;w++) tot += red[w];
    float inv = 1.0f/tot;
    #pragma unroll
    for (int i=0;i<16;i++){
        int idx = i*256 + tid;
        if (!fl[idx>>7]) S[idx] = vals[i]*inv;
    }
}

// ---------------- PV: h[b] = attn[b] @ xv[b]  (NN, skip masked k-tiles) ----------------
__global__ void __launch_bounds__(256,2)
pv_kernel()
{
    const int b = blockIdx.z, qb = blockIdx.y;
    const int bm = qb*128, bn = blockIdx.x*128;
    __shared__ __align__(16) float As[2][16*SA];
    __shared__ __align__(16) float Bs[2][16*SA];
    __shared__ int kbs[32];
    __shared__ int nkb_s;
    const int tid = threadIdx.x;
    if (tid==0){
        int c=0;
        for (int kb=0;kb<32;kb++) if (!g_flags[qb*32+kb]) kbs[c++]=kb;
        nkb_s = c;
    }
    __syncthreads();
    const int nt = nkb_s*8;
    const float* A = g_scores + (size_t)b*SLV*SLV;
    const float* B = g_xv + (size_t)b*SLV*DIMV;

    const int c0=tid, c1=tid+256;
    const int ar0=c0>>2, ak0=(c0&3)*4;
    const int ar1=c1>>2, ak1=(c1&3)*4;
    const int bk0=c0>>5, bn0=(c0&31)*4;
    const int bk1=c1>>5, bn1=(c1&31)*4;

    const int tx=tid&15, ty=tid>>4;
    const int m0=ty*8, n0=tx*8;

    unsigned long long acc[8][4];
    #pragma unroll
    for (int i=0;i<8;i++){
        #pragma unroll
        for (int j=0;j<4;j++) acc[i][j]=0ull;
    }

    int kt = kbs[0]*128;   // t=0
    float4 ra0 = *(const float4*)(A + (size_t)(bm+ar0)*SLV + kt+ak0);
    float4 ra1 = *(const float4*)(A + (size_t)(bm+ar1)*SLV + kt+ak1);
    float4 rb0 = *(const float4*)(B + (size_t)(kt+bk0)*DIMV + bn+bn0);
    float4 rb1 = *(const float4*)(B + (size_t)(kt+bk1)*DIMV + bn+bn1);
    sts4t(As[0],ak0,ar0,ra0); sts4t(As[0],ak1,ar1,ra1);
    *(float4*)&Bs[0][bk0*SA+bn0]=rb0; *(float4*)&Bs[0][bk1*SA+bn1]=rb1;
    __syncthreads();

    for (int t=0; t<nt; t++){
        if (t+1 < nt){
            int t2 = t+1;
            int k2 = kbs[t2>>3]*128 + (t2&7)*16;
            ra0 = *(const float4*)(A + (size_t)(bm+ar0)*SLV + k2+ak0);
            ra1 = *(const float4*)(A + (size_t)(bm+ar1)*SLV + k2+ak1);
            rb0 = *(const float4*)(B + (size_t)(k2+bk0)*DIMV + bn+bn0);
            rb1 = *(const float4*)(B + (size_t)(k2+bk1)*DIMV + bn+bn1);
        }
        mm16(As[t&1], Bs[t&1], m0, n0, acc);
        if (t+1 < nt){
            int bb=(t+1)&1;
            sts4t(As[bb],ak0,ar0,ra0); sts4t(As[bb],ak1,ar1,ra1);
            *(float4*)&Bs[bb][bk0*SA+bn0]=rb0; *(float4*)&Bs[bb][bk1*SA+bn1]=rb1;
            __syncthreads();
        }
    }

    #pragma unroll
    for (int i=0;i<8;i++){
        size_t off = (size_t)(b*SLV + bm+m0+i)*DIMV + bn + n0;
        F2U u0,u1,u2,u3;
        u0.u=acc[i][0]; u1.u=acc[i][1]; u2.u=acc[i][2]; u3.u=acc[i][3];
        float4 o0 = make_float4(u0.f.x,u0.f.y,u1.f.x,u1.f.y);
        float4 o1 = make_float4(u2.f.x,u2.f.y,u3.f.x,u3.f.y);
        *(float4*)(g_h+off)=o0; *(float4*)(g_h+off+4)=o1;
    }
}

// ---------------- launch ----------------
extern "C" void kernel_launch(void* const* d_in, const int* in_sizes, int n_in,
                              void* d_out, int out_size) {
    (void)in_sizes; (void)n_in; (void)out_size;
    const float* x    = (const float*)d_in[0];
    const float* mask = (const float*)d_in[1];
    float* out = (float*)d_out;

    float *Wk,*Wv,*Wo,*W1,*W2,*xk,*xv,*h,*hres,*ff1;
    cudaGetSymbolAddress((void**)&Wk,   g_Wk);
    cudaGetSymbolAddress((void**)&Wv,   g_Wv);
    cudaGetSymbolAddress((void**)&Wo,   g_Wo);
    cudaGetSymbolAddress((void**)&W1,   g_W1);
    cudaGetSymbolAddress((void**)&W2,   g_W2);
    cudaGetSymbolAddress((void**)&xk,   g_xk);
    cudaGetSymbolAddress((void**)&xv,   g_xv);
    cudaGetSymbolAddress((void**)&h,    g_h);
    cudaGetSymbolAddress((void**)&hres, g_hres);
    cudaGetSymbolAddress((void**)&ff1,  g_ff1);

    dim3 blk(256);

    make_w_kernel<<<(DIMV*DIMV+255)/256, blk>>>((const float*)d_in[2],(const float*)d_in[3],(const float*)d_in[4], Wk, DIMV*DIMV);
    make_w_kernel<<<(DIMV*DIMV+255)/256, blk>>>((const float*)d_in[5],(const float*)d_in[6],(const float*)d_in[7], Wv, DIMV*DIMV);
    make_w_kernel<<<(DIMV*DIMV+255)/256, blk>>>((const float*)d_in[8],(const float*)d_in[9],(const float*)d_in[10], Wo, DIMV*DIMV);
    make_w_kernel<<<(HIDV*DIMV+255)/256, blk>>>((const float*)d_in[11],(const float*)d_in[12],(const float*)d_in[13], W1, HIDV*DIMV);
    make_w_kernel<<<(DIMV*HIDV+255)/256, blk>>>((const float*)d_in[14],(const float*)d_in[15],(const float*)d_in[16], W2, DIMV*HIDV);

    // xk = x @ Wk^T ; xv = x @ Wv^T
    gemm_nt_kernel<<<dim3(DIMV/128, TOK/128), blk>>>(x, Wk, xk, nullptr, TOK, DIMV, DIMV, 0);
    gemm_nt_kernel<<<dim3(DIMV/128, TOK/128), blk>>>(x, Wv, xv, nullptr, TOK, DIMV, DIMV, 0);

    // causal tile flags from mask
    flags_kernel<<<dim3(32,32), blk>>>(mask);

    // scores + mask, softmax, attn @ xv
    scores_kernel<<<dim3(32,32,NBATCH), blk>>>(x, mask);
    softmax_kernel<<<TOK, blk>>>();
    pv_kernel<<<dim3(DIMV/128, SLV/128, NBATCH), blk>>>();

    // h_res = x + h @ Wo^T
    gemm_nt_kernel<<<dim3(DIMV/128, TOK/128), blk>>>(h, Wo, hres, x, TOK, DIMV, DIMV, 1);
    // ff1 = relu(h_res @ W1^T)
    gemm_nt_kernel<<<dim3(HIDV/128, TOK/128), blk>>>(hres, W1, ff1, nullptr, TOK, HIDV, DIMV, 2);
    // out = h_res + ff1 @ W2^T
    gemm_nt_kernel<<<dim3(DIMV/128, TOK/128), blk>>>(ff1, W2, out, hres, TOK, DIMV, HIDV, 1);
}